// round 17
// baseline (speedup 1.0000x reference)
#include <cuda_runtime.h>
#include <cuda_bf16.h>
#include <math.h>

// Problem constants
#define BQ   128
#define TQ   256
#define INQ  128
#define HQ   1024
#define NCTA 128      // 32 col-tiles x 4 unit-splits; all co-resident
#define NTHR 512      // 16 warps -> 4 per SMSP

#define NU0  36       // layer0 units of k32: 4 (x) + 32 (h0)
#define TILE16K 16384u
#define STAGEB  32768u
#define NBUF 4

// ---------------------------------------------------------------------------
// Device globals. Operand tiles contiguous + pre-swizzled. h tiles and part
// buffers are PING-PONGED on step parity (dataflow, no per-step grid bars).
// Tile (16KB) = [hi 8KB | lo 8KB]; within 8KB:
// byte off = r*64 + ((seg ^ ((r>>1)&3))<<4) + (k&7)*2,  seg = k>>3.
// ---------------------------------------------------------------------------
__device__ __align__(1024) unsigned char g_W0t[32u * NU0 * TILE16K];
__device__ __align__(1024) unsigned char g_W1t[32u * 64u * TILE16K];
__device__ __align__(1024) unsigned char g_xt[(unsigned)TQ * 4u * TILE16K];
__device__ __align__(1024) unsigned char g_h0t[2][32u * TILE16K];
__device__ __align__(1024) unsigned char g_h1t[2][32u * TILE16K];
__device__ float g_h1f[BQ * HQ];
__device__ float g_c0[BQ * HQ];
__device__ float g_c1[BQ * HQ];
// Partial gate sums (ping-pong): [par][slot*32+tile][b][c]
__device__ float g_part0[2][2u * 32u * 128u * 128u];
__device__ float g_part1[2][3u * 32u * 128u * 128u];

// Dataflow counters (monotone within one replay; reset by init):
//  hc*  = h-tile produced epochs, pc* = part produced, pcc* = part CONSUMED
__device__ int g_hc0[32];
__device__ int g_hc1[32];
__device__ int g_pc0[32];
__device__ int g_pc1[32];
__device__ int g_pcc0[32];
__device__ int g_pcc1[32];

__device__ unsigned g_bar_count = 0;
__device__ unsigned g_bar_gen   = 0;

__device__ __forceinline__ unsigned off_in_tile(int r, int k) {
    return (unsigned)(r * 64 + ((((k >> 3) ^ ((r >> 1) & 3))) << 4) + ((k & 7) << 1));
}

// ---------------------------------------------------------------------------
// PTX helpers (sm_80/90 baseline — no 'a'-gated features)
// ---------------------------------------------------------------------------
__device__ __forceinline__ unsigned smem_u32(const void* p) {
    unsigned a;
    asm("{ .reg .u64 t; cvta.to.shared.u64 t, %1; cvt.u32.u64 %0, t; }"
        : "=r"(a) : "l"(p));
    return a;
}
__device__ __forceinline__ void mbar_init(unsigned mbar, unsigned cnt) {
    asm volatile("mbarrier.init.shared.b64 [%0], %1;" :: "r"(mbar), "r"(cnt) : "memory");
}
__device__ __forceinline__ void mbar_wait(unsigned mbar, unsigned parity) {
    asm volatile(
        "{\n\t.reg .pred P;\n\t"
        "W_%=:\n\t"
        "mbarrier.try_wait.parity.acquire.cta.shared::cta.b64 P, [%0], %1, 0x989680;\n\t"
        "@!P bra W_%=;\n\t}"
        :: "r"(mbar), "r"(parity) : "memory");
}
__device__ __forceinline__ void mbar_expect_tx(unsigned mbar, unsigned bytes) {
    asm volatile("mbarrier.arrive.expect_tx.shared.b64 _, [%0], %1;"
                 :: "r"(mbar), "r"(bytes) : "memory");
}
__device__ __forceinline__ void bulk_g2s(unsigned dst, const void* src,
                                         unsigned bytes, unsigned mbar) {
    asm volatile(
        "cp.async.bulk.shared::cluster.global.mbarrier::complete_tx::bytes "
        "[%0], [%1], %2, [%3];"
        :: "r"(dst), "l"(src), "r"(bytes), "r"(mbar) : "memory");
}
__device__ __forceinline__ void fence_async() {
    asm volatile("fence.proxy.async.shared::cta;" ::: "memory");
}
__device__ __forceinline__ void ldsm4(unsigned& r0, unsigned& r1,
                                      unsigned& r2, unsigned& r3, unsigned a) {
    asm volatile("ldmatrix.sync.aligned.m8n8.x4.shared.b16 {%0,%1,%2,%3}, [%4];"
                 : "=r"(r0), "=r"(r1), "=r"(r2), "=r"(r3) : "r"(a));
}
__device__ __forceinline__ void mma16816(float* d, const unsigned* a, const unsigned* b) {
    asm volatile(
        "mma.sync.aligned.m16n8k16.row.col.f32.bf16.bf16.f32 "
        "{%0,%1,%2,%3}, {%4,%5,%6,%7}, {%8,%9}, {%0,%1,%2,%3};"
        : "+f"(d[0]), "+f"(d[1]), "+f"(d[2]), "+f"(d[3])
        : "r"(a[0]), "r"(a[1]), "r"(a[2]), "r"(a[3]), "r"(b[0]), "r"(b[1]));
}

// Spin until *p >= thr (volatile, L2-coherent); trailing fence = acquire +
// L1 invalidate so subsequent normal loads see fresh data.
__device__ __forceinline__ void spin_ge(const int* p, int thr) {
    while (*(const volatile int*)p < thr) { }
    __threadfence();
}

// ---------------------------------------------------------------------------
// Grid barrier (used ONCE before the dense head)
// ---------------------------------------------------------------------------
__device__ __forceinline__ void grid_bar() {
    __threadfence();
    __syncthreads();
    if (threadIdx.x == 0) {
        unsigned my = *(volatile unsigned*)&g_bar_gen;
        if (atomicAdd(&g_bar_count, 1u) == NCTA - 1u) {
            *(volatile unsigned*)&g_bar_count = 0;
            __threadfence();
            atomicExch(&g_bar_gen, my + 1u);
        } else {
            while (*(volatile unsigned*)&g_bar_gen == my) { }
        }
        __threadfence();
    }
    __syncthreads();
}

// ---------------------------------------------------------------------------
// Init kernels (per replay; deterministic)
// ---------------------------------------------------------------------------
__device__ __forceinline__ void split_store(float v, unsigned char* hi_ptr) {
    __nv_bfloat16 h = __float2bfloat16(v);
    __nv_bfloat16 l = __float2bfloat16(v - __bfloat162float(h));
    *(__nv_bfloat16*)hi_ptr = h;
    *(__nv_bfloat16*)(hi_ptr + 8192) = l;
}

__global__ void init_state_kernel() {
    int i = blockIdx.x * blockDim.x + threadIdx.x;
    if (i < (32 * 16384) / 4) {
        ((unsigned*)g_h0t[0])[i] = 0u; ((unsigned*)g_h0t[1])[i] = 0u;
        ((unsigned*)g_h1t[0])[i] = 0u; ((unsigned*)g_h1t[1])[i] = 0u;
    }
    if (i < BQ * HQ) { g_c0[i] = 0.f; g_c1[i] = 0.f; }
    if (i < 32) {
        g_hc0[i] = 0; g_hc1[i] = 0;
        g_pc0[i] = 0; g_pc1[i] = 0;
        g_pcc0[i] = 0; g_pcc1[i] = 0;
    }
}
__global__ void init_x_kernel(const float* __restrict__ x) {
    int i = blockIdx.x * blockDim.x + threadIdx.x;   // = b*32768 + t*128 + k
    if (i >= BQ * TQ * INQ) return;
    int k = i & 127, t = (i >> 7) & 255, b = i >> 15;
    int u = k >> 5, kl = k & 31;
    unsigned char* dst = g_xt + (size_t)(t * 4 + u) * TILE16K + off_in_tile(b, kl);
    split_store(x[i], dst);
}
__global__ void init_w_kernel(
    const float* __restrict__ W_ih0, const float* __restrict__ W_hh0,
    const float* __restrict__ W_ih1, const float* __restrict__ W_hh1)
{
    const unsigned N0 = 32u * NU0 * 4096u;
    const unsigned N1 = 32u * 64u * 4096u;
    for (unsigned i = blockIdx.x * blockDim.x + threadIdx.x; i < N0 + N1;
         i += gridDim.x * blockDim.x) {
        if (i < N0) {
            unsigned kl = i & 31u, r = (i >> 5) & 127u;
            unsigned rest = i >> 12, u = rest % NU0, tile = rest / NU0;
            unsigned gcol = ((r >> 5) << 10) + tile * 32u + (r & 31u);
            unsigned k = u * 32u + kl;
            float v = (k < 128u) ? W_ih0[(size_t)gcol * 128u + k]
                                 : W_hh0[(size_t)gcol * 1024u + (k - 128u)];
            split_store(v, g_W0t + (size_t)(tile * NU0 + u) * TILE16K + off_in_tile(r, kl));
        } else {
            unsigned j = i - N0;
            unsigned kl = j & 31u, r = (j >> 5) & 127u;
            unsigned rest = j >> 12, u = rest & 63u, tile = rest >> 6;
            unsigned gcol = ((r >> 5) << 10) + tile * 32u + (r & 31u);
            unsigned k = u * 32u + kl;
            float v = (k < 1024u) ? W_ih1[(size_t)gcol * 1024u + k]
                                  : W_hh1[(size_t)gcol * 1024u + (k - 1024u)];
            split_store(v, g_W1t + (size_t)(tile * 64u + u) * TILE16K + off_in_tile(r, kl));
        }
    }
}

// ---------------------------------------------------------------------------
// Cell update for tile j, batch rows [s*32, s*32+32). 512 thr x 2 cells each.
// Spins on the tile's part-produced counter; publishes h-produced AND
// part-consumed counters.
// ---------------------------------------------------------------------------
template <int NS>
__device__ void cell_tile(
    int j, int s, const int* pc, int pthr, int* hcnt, int* ccnt,
    float* __restrict__ cst, unsigned char* __restrict__ hw,
    float* __restrict__ hf, const float* __restrict__ part,
    const float* __restrict__ b_ih, const float* __restrict__ b_hh)
{
    const int tid = threadIdx.x;
    if (tid == 0) spin_ge(pc + j, pthr);
    __syncthreads();

    int b  = s * 32 + (tid >> 4);
    int nl = (tid & 15) * 2;
    int n  = j * 32 + nl;

    #pragma unroll
    for (int e = 0; e < 2; ++e) {
        float g4[4];
        #pragma unroll
        for (int g = 0; g < 4; ++g) {
            float sum = b_ih[g * 1024 + n + e] + b_hh[g * 1024 + n + e];
            #pragma unroll
            for (int s2 = 0; s2 < NS; ++s2)
                sum += part[((size_t)(s2 * 32 + j) << 14)
                            + (size_t)b * 128 + g * 32 + nl + e];
            g4[g] = sum;
        }
        float si = 1.f / (1.f + expf(-g4[0]));
        float sf = 1.f / (1.f + expf(-g4[1]));
        float so = 1.f / (1.f + expf(-g4[3]));
        int gid = b * 1024 + n + e;
        float cn = sf * cst[gid] + si * tanhf(g4[2]);
        cst[gid] = cn;
        float hv = so * tanhf(cn);
        split_store(hv, hw + (size_t)j * TILE16K + off_in_tile(b, nl + e));
        if (hf) hf[gid] = hv;
    }

    __threadfence();      // publish h writes; order part loads before bumps
    __syncthreads();
    if (tid == 0) {
        atomicAdd(hcnt + j, 1);
        atomicAdd(ccnt + j, 1);
    }
}

// ---------------------------------------------------------------------------
// GEMM segment. Per k32 unit: issuer spins on the unit's h-tile counter, then
// 2 bulk copies; mbarrier pipeline; 3-term split bf16 HMMA (term-outer).
// Warp grid 4(M) x 4(N), warp tile 32x32.
// Epilogue WAR-gate: spin ccnt >= cthr (previous parity's readers done)
// before the partial stores. MMA compute is NOT gated.
// ---------------------------------------------------------------------------
__device__ void gemm_seg(
    const unsigned char* __restrict__ pxa, int uxsplit,
    const int* cnt1, int thr1,
    const unsigned char* __restrict__ pha,
    const int* cnt2, int thr2,
    const unsigned char* __restrict__ pw,
    int ulo, int nU, float* __restrict__ pslot,
    unsigned sb, unsigned* ph,
    const int* ccnt, int cthr)
{
    const int tid  = threadIdx.x;
    const int lane = tid & 31;
    const int wid  = tid >> 5;
    const int wm   = wid >> 2;   // 0..3
    const int wn   = wid & 3;    // 0..3

    float acc[2][4][4];
    #pragma unroll
    for (int m = 0; m < 2; ++m)
        #pragma unroll
        for (int n = 0; n < 4; ++n)
            #pragma unroll
            for (int r = 0; r < 4; ++r) acc[m][n][r] = 0.f;

    auto issue = [&](int idx) {
        int u = ulo + idx;
        const unsigned char* asrc;
        if (u < uxsplit) {
            if (cnt1) spin_ge(cnt1 + u, thr1);
            asrc = pxa + (size_t)u * TILE16K;
        } else {
            if (cnt2) spin_ge(cnt2 + (u - uxsplit), thr2);
            asrc = pha + (size_t)(u - uxsplit) * TILE16K;
        }
        const unsigned char* wsrc = pw + (size_t)u * TILE16K;
        int buf = idx & (NBUF - 1);
        unsigned mbar = sb + (unsigned)buf * 8u;
        unsigned dst  = sb + 1024u + (unsigned)buf * STAGEB;
        mbar_expect_tx(mbar, STAGEB);
        bulk_g2s(dst,            asrc, TILE16K, mbar);
        bulk_g2s(dst + TILE16K,  wsrc, TILE16K, mbar);
    };

    if (tid == 0) {
        int np = nU < NBUF ? nU : NBUF;
        for (int p = 0; p < np; ++p) issue(p);
    }

    for (int i = 0; i < nU; ++i) {
        int buf = i & (NBUF - 1);
        mbar_wait(sb + (unsigned)buf * 8u, ph[buf]);
        ph[buf] ^= 1u;
        unsigned bA = sb + 1024u + (unsigned)buf * STAGEB;   // A hi (lo +8192)
        unsigned bW = bA + TILE16K;                          // W hi (lo +8192)

        #pragma unroll
        for (int j = 0; j < 2; ++j) {
            int rA = wm * 32 + (lane & 15);
            unsigned aH = bA + (unsigned)(rA * 64)
                        + ((unsigned)((j * 2 + (lane >> 4)) ^ ((rA >> 1) & 3)) << 4);
            unsigned AH[2][4], AL[2][4];
            #pragma unroll
            for (int m = 0; m < 2; ++m) {
                ldsm4(AH[m][0], AH[m][1], AH[m][2], AH[m][3], aH + m * 1024u);
                ldsm4(AL[m][0], AL[m][1], AL[m][2], AL[m][3], aH + m * 1024u + 8192u);
            }
            unsigned WH[4][2], WL[4][2];
            #pragma unroll
            for (int np = 0; np < 2; ++np) {
                int nn = np * 2 + (lane >> 4);
                int rW = wn * 32 + nn * 8 + (lane & 7);
                unsigned wAddr = bW + (unsigned)(rW * 64)
                    + ((unsigned)((j * 2 + ((lane >> 3) & 1)) ^ ((rW >> 1) & 3)) << 4);
                ldsm4(WH[np*2][0], WH[np*2][1], WH[np*2+1][0], WH[np*2+1][1], wAddr);
                ldsm4(WL[np*2][0], WL[np*2][1], WL[np*2+1][0], WL[np*2+1][1],
                      wAddr + 8192u);
            }
            if (j == 1) {
                __syncthreads();     // all threads done reading this buffer
                if (tid == 0 && i + NBUF < nU) issue(i + NBUF);
            }
            #pragma unroll
            for (int m = 0; m < 2; ++m)
                #pragma unroll
                for (int n = 0; n < 4; ++n)
                    mma16816(acc[m][n], AH[m], WH[n]);
            #pragma unroll
            for (int m = 0; m < 2; ++m)
                #pragma unroll
                for (int n = 0; n < 4; ++n)
                    mma16816(acc[m][n], AL[m], WH[n]);
            #pragma unroll
            for (int m = 0; m < 2; ++m)
                #pragma unroll
                for (int n = 0; n < 4; ++n)
                    mma16816(acc[m][n], AH[m], WL[n]);
        }
    }

    // WAR gate: previous-parity readers of this part slot must be done.
    if (tid == 0) spin_ge(ccnt, cthr);
    __syncthreads();

    // Epilogue: D fragments -> pslot[b][c]
    #pragma unroll
    for (int m = 0; m < 2; ++m)
        #pragma unroll
        for (int n = 0; n < 4; ++n) {
            int b = wm * 32 + m * 16 + (lane >> 2);
            int c = wn * 32 + n * 8 + (lane & 3) * 2;
            *(float2*)(pslot + (size_t)b * 128 + c) =
                make_float2(acc[m][n][0], acc[m][n][1]);
            *(float2*)(pslot + (size_t)(b + 8) * 128 + c) =
                make_float2(acc[m][n][2], acc[m][n][3]);
        }
}

// Publish a part slot: fence all threads' epilogue stores, then bump counter.
__device__ __forceinline__ void publish_part(int* pc, int tile) {
    __threadfence();
    __syncthreads();
    if (threadIdx.x == 0) atomicAdd(pc + tile, 1);
}

// ---------------------------------------------------------------------------
// Main persistent kernel: tile-granular dataflow, NO per-step grid barriers.
// Per step t: G = gemm0(t) [t<TQ] + gemm1(t-1) [t>0]; C = cell0(t) + cell1(t-1).
// Unit splits: s0: L0[0,25); s1: L0[25,36) + L1[0,14); s2: L1[14,39); s3: L1[39,64).
// L1 units: u<32 -> A = h0 tile u; u>=32 -> A = h1 tile u-32.
// L0 units: u<4 -> A = x chunk u; u>=4 -> A = h0 tile u-4.
// ---------------------------------------------------------------------------
__global__ __launch_bounds__(NTHR, 1) void lstm_mma_kernel(
    const float* __restrict__ b_ih0, const float* __restrict__ b_hh0,
    const float* __restrict__ b_ih1, const float* __restrict__ b_hh1,
    const float* __restrict__ Wd,    const float* __restrict__ bd,
    float* __restrict__ out)
{
    extern __shared__ __align__(1024) unsigned char dsmem[];
    const unsigned sb = smem_u32(dsmem);
    const int tid  = threadIdx.x;
    const int cta  = blockIdx.x;
    const int tile = cta & 31;
    const int s    = cta >> 5;

    if (tid == 0) {
        #pragma unroll
        for (int i = 0; i < NBUF; ++i) mbar_init(sb + i * 8u, 1u);
        fence_async();
    }
    __syncthreads();

    unsigned ph[NBUF] = {0, 0, 0, 0};

    const unsigned char* w0 = g_W0t + (size_t)tile * NU0 * TILE16K;
    const unsigned char* w1 = g_W1t + (size_t)tile * 64u * TILE16K;

    for (int t = 0; t <= TQ; ++t) {
        const int pr  = t & 1;          // h0 read parity (version t), part0 parity
        const int prm = (t - 1) & 1;    // h1 read parity (version t-1), part1 parity
        const unsigned char* h0r = g_h0t[pr];
        const unsigned char* h1r = g_h1t[prm];
        float* part0w = g_part0[pr];
        float* part1w = g_part1[prm];

        // ---- G: gemm0(t) and gemm1(t-1)
        if (s == 0) {
            if (t < TQ) {
                gemm_seg(g_xt + (size_t)t * 4 * TILE16K, 4, nullptr, 0,
                         h0r, g_hc0, 4 * t,      // h0 tile (u-4), counter hc0[u-4]
                         w0, 0, 25,
                         part0w + ((size_t)(0 * 32 + tile) << 14), sb, ph,
                         g_pcc0 + tile, 4 * t - 4);
                publish_part(g_pc0, tile);
            }
        } else if (s == 1) {
            if (t < TQ) {
                gemm_seg(g_xt + (size_t)t * 4 * TILE16K, 4, nullptr, 0,
                         h0r, g_hc0, 4 * t,
                         w0, 25, 11,
                         part0w + ((size_t)(1 * 32 + tile) << 14), sb, ph,
                         g_pcc0 + tile, 4 * t - 4);
                publish_part(g_pc0, tile);
            }
            if (t > 0) {
                gemm_seg(h0r, 32, g_hc0, 4 * t,
                         h1r, g_hc1, 4 * (t - 1),
                         w1, 0, 14,
                         part1w + ((size_t)(0 * 32 + tile) << 14), sb, ph,
                         g_pcc1 + tile, 4 * t - 8);
                publish_part(g_pc1, tile);
            }
        } else if (s == 2) {
            if (t > 0) {
                gemm_seg(h0r, 32, g_hc0, 4 * t,
                         h1r, g_hc1, 4 * (t - 1),
                         w1, 14, 25,
                         part1w + ((size_t)(1 * 32 + tile) << 14), sb, ph,
                         g_pcc1 + tile, 4 * t - 8);
                publish_part(g_pc1, tile);
            }
        } else {
            if (t > 0) {
                gemm_seg(h0r, 32, g_hc0, 4 * t,
                         h1r, g_hc1, 4 * (t - 1),
                         w1, 39, 25,
                         part1w + ((size_t)(2 * 32 + tile) << 14), sb, ph,
                         g_pcc1 + tile, 4 * t - 8);
                publish_part(g_pc1, tile);
            }
        }

        // ---- C: cell0(t) then cell1(t-1)
        if (t < TQ)
            cell_tile<2>(tile, s, g_pc0, 2 * (t + 1), g_hc0, g_pcc0,
                         g_c0, g_h0t[(t + 1) & 1], nullptr,
                         g_part0[pr], b_ih0, b_hh0);
        if (t > 0)
            cell_tile<3>(tile, s, g_pc1, 3 * t, g_hc1, g_pcc1,
                         g_c1, g_h1t[t & 1], (t == TQ) ? g_h1f : nullptr,
                         g_part1[prm], b_ih1, b_hh1);
    }

    grid_bar();   // all h1f visible

    // Dense head: CTA b computes out[b][0..1] from fp32 h1
    {
        float* red = (float*)dsmem;
        const int b = cta;
        const int lane = tid & 31;
        const int wid  = tid >> 5;
        float s0 = 0.f, s1 = 0.f;
        for (int n = tid; n < HQ; n += NTHR) {
            float hv = g_h1f[(size_t)b * HQ + n];
            s0 += hv * Wd[n];
            s1 += hv * Wd[HQ + n];
        }
        #pragma unroll
        for (int off = 16; off > 0; off >>= 1) {
            s0 += __shfl_down_sync(0xffffffffu, s0, off);
            s1 += __shfl_down_sync(0xffffffffu, s1, off);
        }
        __syncthreads();
        if (lane == 0) { red[wid] = s0; red[16 + wid] = s1; }
        __syncthreads();
        if (tid == 0) {
            float a0 = 0.f, a1 = 0.f;
            #pragma unroll
            for (int w = 0; w < NTHR / 32; ++w) { a0 += red[w]; a1 += red[16 + w]; }
            out[b * 2 + 0] = tanhf(a0 + bd[0]);
            out[b * 2 + 1] = tanhf(a1 + bd[1]);
        }
    }
}

// ---------------------------------------------------------------------------
// Launch: 4 graph nodes
// ---------------------------------------------------------------------------
extern "C" void kernel_launch(void* const* d_in, const int* in_sizes, int n_in,
                              void* d_out, int out_size)
{
    const float* x     = (const float*)d_in[0];
    const float* W_ih0 = (const float*)d_in[1];
    const float* W_hh0 = (const float*)d_in[2];
    const float* b_ih0 = (const float*)d_in[3];
    const float* b_hh0 = (const float*)d_in[4];
    const float* W_ih1 = (const float*)d_in[5];
    const float* W_hh1 = (const float*)d_in[6];
    const float* b_ih1 = (const float*)d_in[7];
    const float* b_hh1 = (const float*)d_in[8];
    const float* Wd    = (const float*)d_in[9];
    const float* bd    = (const float*)d_in[10];
    float* out = (float*)d_out;

    const int smem_bytes = 1024 + NBUF * (int)STAGEB;   // 132096
    cudaFuncSetAttribute(lstm_mma_kernel,
                         cudaFuncAttributeMaxDynamicSharedMemorySize, smem_bytes);

    init_state_kernel<<<(32 * 16384 / 4 + 255) / 256, 256>>>();
    init_x_kernel<<<(BQ * TQ * INQ + 255) / 256, 256>>>(x);
    init_w_kernel<<<2048, 256>>>(W_ih0, W_hh0, W_ih1, W_hh1);

    lstm_mma_kernel<<<NCTA, NTHR, smem_bytes>>>(
        b_ih0, b_hh0, b_ih1, b_hh1, Wd, bd, out);
}